// round 10
// baseline (speedup 1.0000x reference)
#include <cuda_runtime.h>
#include <cstdint>

// x: (2, 3, 256, 256, 256) float32 ; out: (2, 256, 256, 256) float32
//
// out[b,z,y,i] = 0.5 * ( u[b,z,y,(i+1)&255] - u[b,z,y,(i-1)&255]
//                      + v[b,z,(y+1)&255,i] - v[b,z,(y-1)&255,i]
//                      + w[b,(z+1)&255,(y+1)&255,i] - w[b,(z-1)&255,(y-1)&255,i] )
//
// Plateau body (ncu 74.7-74.9us, DRAM 87%, HBM 6.9 TB/s on minimal ~537 MB
// traffic). This round probes the last untried config knob: block=128
// (finer CTA granularity -> shallower per-CTA L1tex bursts, finer wave
// tails). Body is byte-identical to the best-measured kernel.

#define DIM 256
#define DIMM 255
#define Q 64
#define VOL (DIM * DIM * DIM)

__global__ __launch_bounds__(128) void calc_divergence_kernel(
    const float* __restrict__ x, float* __restrict__ out)
{
    const uint32_t idx = blockIdx.x * blockDim.x + threadIdx.x;
    // decompose: [b:1][z:8][y:8][xq:6]
    const uint32_t xq = idx & (Q - 1);
    const uint32_t y  = (idx >> 6) & DIMM;
    const uint32_t z  = (idx >> 14) & DIMM;
    const uint32_t b  = idx >> 22;

    const uint32_t i0 = xq << 2;

    const uint32_t yp = (y + 1) & DIMM;
    const uint32_t ym = (y - 1) & DIMM;
    const uint32_t zp = (z + 1) & DIMM;
    const uint32_t zm = (z - 1) & DIMM;

    // 32-bit row offsets within one field (max 2^24, fits)
    const uint32_t offc  = ((z  << 8) + y ) << 8;
    const uint32_t offvp = ((z  << 8) + yp) << 8;
    const uint32_t offvm = ((z  << 8) + ym) << 8;
    const uint32_t offwp = ((zp << 8) + yp) << 8;
    const uint32_t offwm = ((zm << 8) + ym) << 8;

    const float* u = x + (size_t)(b * 3 + 0) * VOL;
    const float* v = x + (size_t)(b * 3 + 1) * VOL;
    const float* w = x + (size_t)(b * 3 + 2) * VOL;
    const float* urow = u + offc;

    // ---- all global loads back-to-back (uniform MLP) ----
    const float4 uc = *reinterpret_cast<const float4*>(urow + i0);
    const float4 vp = *reinterpret_cast<const float4*>(v + offvp + i0);
    const float4 vm = *reinterpret_cast<const float4*>(v + offvm + i0);
    const float4 wp = *reinterpret_cast<const float4*>(w + offwp + i0);
    const float4 wm = *reinterpret_cast<const float4*>(w + offwm + i0);
    const float  ul = urow[(i0 - 1) & DIMM];
    const float  ur = urow[(i0 + 4) & DIMM];

    float4 r;
    r.x = 0.5f * ((uc.y - ul)   + (vp.x - vm.x) + (wp.x - wm.x));
    r.y = 0.5f * ((uc.z - uc.x) + (vp.y - vm.y) + (wp.y - wm.y));
    r.z = 0.5f * ((uc.w - uc.y) + (vp.z - vm.z) + (wp.z - wm.z));
    r.w = 0.5f * ((ur   - uc.z) + (vp.w - vm.w) + (wp.w - wm.w));

    *reinterpret_cast<float4*>(out + (size_t)b * VOL + offc + i0) = r;
}

extern "C" void kernel_launch(void* const* d_in, const int* in_sizes, int n_in,
                              void* d_out, int out_size)
{
    const float* x = (const float*)d_in[0];
    float* out = (float*)d_out;

    const uint32_t total_f4 = 2u * DIM * DIM * Q;   // 8,388,608
    const uint32_t threads = 128;
    const uint32_t blocks = total_f4 / threads;     // 65,536

    calc_divergence_kernel<<<blocks, threads>>>(x, out);
}

// round 11
// speedup vs baseline: 1.0078x; 1.0078x over previous
#include <cuda_runtime.h>
#include <cstdint>

// x: (2, 3, 256, 256, 256) float32 ; out: (2, 256, 256, 256) float32
//
// out[b,z,y,i] = 0.5 * ( u[b,z,y,(i+1)&255] - u[b,z,y,(i-1)&255]
//                      + v[b,z,(y+1)&255,i] - v[b,z,(y-1)&255,i]
//                      + w[b,(z+1)&255,(y+1)&255,i] - w[b,(z-1)&255,(y-1)&255,i] )
//
// FINAL (10 rounds). One thread per output float4 (8,388,608 threads),
// block=256, 32 regs, 83% occupancy. ncu: 74.7-74.9us, DRAM=87.3%,
// HBM 6.92 TB/s (86.5% of 8 TB/s spec) moving the provably-minimal
// ~537 MB (all stencil-neighbor reuse absorbed by L2/L1) — the kernel is
// HBM-stream-efficiency saturated. Full variant ledger:
//   2x float4/thread  -> 79.0us, occ 63%   (REGRESS)
//   shuffle u-edges   -> 77.2us, SHFL serialization (REGRESS)
//   persistent grid   -> 76.2us, loop overhead (REGRESS)
//   __stcs stores     -> neutral
//   block=512         -> 75.4us (neutral-)
//   block=128         -> 75.2us (neutral-)
//   ALU-diet indexing -> neutral (kept: cleanest codegen)

#define DIM 256
#define DIMM 255
#define Q 64
#define VOL (DIM * DIM * DIM)

__global__ __launch_bounds__(256) void calc_divergence_kernel(
    const float* __restrict__ x, float* __restrict__ out)
{
    const uint32_t idx = blockIdx.x * blockDim.x + threadIdx.x;
    // decompose: [b:1][z:8][y:8][xq:6]
    const uint32_t xq = idx & (Q - 1);
    const uint32_t y  = (idx >> 6) & DIMM;
    const uint32_t z  = (idx >> 14) & DIMM;
    const uint32_t b  = idx >> 22;

    const uint32_t i0 = xq << 2;

    const uint32_t yp = (y + 1) & DIMM;
    const uint32_t ym = (y - 1) & DIMM;
    const uint32_t zp = (z + 1) & DIMM;
    const uint32_t zm = (z - 1) & DIMM;

    // 32-bit row offsets within one field (max 2^24, fits)
    const uint32_t offc  = ((z  << 8) + y ) << 8;
    const uint32_t offvp = ((z  << 8) + yp) << 8;
    const uint32_t offvm = ((z  << 8) + ym) << 8;
    const uint32_t offwp = ((zp << 8) + yp) << 8;
    const uint32_t offwm = ((zm << 8) + ym) << 8;

    const float* u = x + (size_t)(b * 3 + 0) * VOL;
    const float* v = x + (size_t)(b * 3 + 1) * VOL;
    const float* w = x + (size_t)(b * 3 + 2) * VOL;
    const float* urow = u + offc;

    // ---- all global loads back-to-back (uniform MLP) ----
    const float4 uc = *reinterpret_cast<const float4*>(urow + i0);
    const float4 vp = *reinterpret_cast<const float4*>(v + offvp + i0);
    const float4 vm = *reinterpret_cast<const float4*>(v + offvm + i0);
    const float4 wp = *reinterpret_cast<const float4*>(w + offwp + i0);
    const float4 wm = *reinterpret_cast<const float4*>(w + offwm + i0);
    const float  ul = urow[(i0 - 1) & DIMM];
    const float  ur = urow[(i0 + 4) & DIMM];

    float4 r;
    r.x = 0.5f * ((uc.y - ul)   + (vp.x - vm.x) + (wp.x - wm.x));
    r.y = 0.5f * ((uc.z - uc.x) + (vp.y - vm.y) + (wp.y - wm.y));
    r.z = 0.5f * ((uc.w - uc.y) + (vp.z - vm.z) + (wp.z - wm.z));
    r.w = 0.5f * ((ur   - uc.z) + (vp.w - vm.w) + (wp.w - wm.w));

    *reinterpret_cast<float4*>(out + (size_t)b * VOL + offc + i0) = r;
}

extern "C" void kernel_launch(void* const* d_in, const int* in_sizes, int n_in,
                              void* d_out, int out_size)
{
    const float* x = (const float*)d_in[0];
    float* out = (float*)d_out;

    const uint32_t total_f4 = 2u * DIM * DIM * Q;   // 8,388,608
    const uint32_t threads = 256;
    const uint32_t blocks = total_f4 / threads;     // 32,768

    calc_divergence_kernel<<<blocks, threads>>>(x, out);
}

// round 12
// speedup vs baseline: 1.0082x; 1.0004x over previous
#include <cuda_runtime.h>
#include <cstdint>

// x: (2, 3, 256, 256, 256) float32 ; out: (2, 256, 256, 256) float32
//
// out[b,z,y,i] = 0.5 * ( u[b,z,y,(i+1)&255] - u[b,z,y,(i-1)&255]
//                      + v[b,z,(y+1)&255,i] - v[b,z,(y-1)&255,i]
//                      + w[b,(z+1)&255,(y+1)&255,i] - w[b,(z-1)&255,(y-1)&255,i] )
//
// Plateau body (ncu 74.7-75.3us, DRAM 87%, HBM 6.9 TB/s, minimal traffic).
// This round: __ldcg (L2-only) on the v/w neighbor loads — their reuse is
// cross-CTA via L2; keeping them out of L1 preserves L1 for the u rows
// that the scalar edge loads hit. Everything else identical to best.

#define DIM 256
#define DIMM 255
#define Q 64
#define VOL (DIM * DIM * DIM)

__global__ __launch_bounds__(256) void calc_divergence_kernel(
    const float* __restrict__ x, float* __restrict__ out)
{
    const uint32_t idx = blockIdx.x * blockDim.x + threadIdx.x;
    // decompose: [b:1][z:8][y:8][xq:6]
    const uint32_t xq = idx & (Q - 1);
    const uint32_t y  = (idx >> 6) & DIMM;
    const uint32_t z  = (idx >> 14) & DIMM;
    const uint32_t b  = idx >> 22;

    const uint32_t i0 = xq << 2;

    const uint32_t yp = (y + 1) & DIMM;
    const uint32_t ym = (y - 1) & DIMM;
    const uint32_t zp = (z + 1) & DIMM;
    const uint32_t zm = (z - 1) & DIMM;

    // 32-bit row offsets within one field (max 2^24, fits)
    const uint32_t offc  = ((z  << 8) + y ) << 8;
    const uint32_t offvp = ((z  << 8) + yp) << 8;
    const uint32_t offvm = ((z  << 8) + ym) << 8;
    const uint32_t offwp = ((zp << 8) + yp) << 8;
    const uint32_t offwm = ((zm << 8) + ym) << 8;

    const float* u = x + (size_t)(b * 3 + 0) * VOL;
    const float* v = x + (size_t)(b * 3 + 1) * VOL;
    const float* w = x + (size_t)(b * 3 + 2) * VOL;
    const float* urow = u + offc;

    // ---- all global loads back-to-back (uniform MLP) ----
    // u row: default (L1-cached — scalar edge loads below hit these lines)
    const float4 uc = *reinterpret_cast<const float4*>(urow + i0);
    // v/w rows: L2-only (reuse is cross-CTA via L2; don't pollute L1)
    const float4 vp = __ldcg(reinterpret_cast<const float4*>(v + offvp + i0));
    const float4 vm = __ldcg(reinterpret_cast<const float4*>(v + offvm + i0));
    const float4 wp = __ldcg(reinterpret_cast<const float4*>(w + offwp + i0));
    const float4 wm = __ldcg(reinterpret_cast<const float4*>(w + offwm + i0));
    const float  ul = urow[(i0 - 1) & DIMM];
    const float  ur = urow[(i0 + 4) & DIMM];

    float4 r;
    r.x = 0.5f * ((uc.y - ul)   + (vp.x - vm.x) + (wp.x - wm.x));
    r.y = 0.5f * ((uc.z - uc.x) + (vp.y - vm.y) + (wp.y - wm.y));
    r.z = 0.5f * ((uc.w - uc.y) + (vp.z - vm.z) + (wp.z - wm.z));
    r.w = 0.5f * ((ur   - uc.z) + (vp.w - vm.w) + (wp.w - wm.w));

    *reinterpret_cast<float4*>(out + (size_t)b * VOL + offc + i0) = r;
}

extern "C" void kernel_launch(void* const* d_in, const int* in_sizes, int n_in,
                              void* d_out, int out_size)
{
    const float* x = (const float*)d_in[0];
    float* out = (float*)d_out;

    const uint32_t total_f4 = 2u * DIM * DIM * Q;   // 8,388,608
    const uint32_t threads = 256;
    const uint32_t blocks = total_f4 / threads;     // 32,768

    calc_divergence_kernel<<<blocks, threads>>>(x, out);
}